// round 14
// baseline (speedup 1.0000x reference)
#include <cuda_runtime.h>
#include <cstdint>

// HashGrid trilinear interpolation + gradient, GB300 sm_103a.
//   d_in[0]: x           (N,3)        float32   N = in_sizes[0]/3
//   d_in[1]: feat_params (CAP,520,5)  float32
//   d_in[2]: block_table (32,32,32)   int32
// Output: concat [feats (N,5) | dfeats_dx (N,5,3) | masks (N)] float32.
//
// R9 structure: 2 lanes per point split by cz (lane&1) so the pair's records
// (20B apart) share L1 lines; 8 LDG.128 per lane batched back-to-back; pair
// reduce via shfl_xor(1); warp-staged coalesced float4 streaming stores.
// R13: cache-hinted gather loads (asm) -> regs 40, occ 65%.
// R14 delta: evict_last FRACTION 1.0 -> 0.5. At 1.0 the whole 208MB table
// competes for the protected partition and thrashes itself (measured: zero
// traffic reduction). At 0.5 a ~104MB stable subset fits in the 126MB L2 and
// hits at steady state.

#define RR 8
#define GG 32
#define FF 5
#define STRIDE_ 520
#define INV_V 100.0f   // 1/0.01f == 100.0f exactly; XLA folds x/V -> x*INV_V

static __device__ __forceinline__ float4 ldg_el(const void* p, uint64_t pol)
{
    float4 r;
    asm volatile("ld.global.nc.L2::cache_hint.v4.f32 {%0,%1,%2,%3}, [%4], %5;"
                 : "=f"(r.x), "=f"(r.y), "=f"(r.z), "=f"(r.w)
                 : "l"(p), "l"(pol));
    return r;
}

__global__ void __launch_bounds__(256)
hashgrid_kernel(const float* __restrict__ x,
                const float* __restrict__ feat,
                const int*   __restrict__ btab,
                float* __restrict__ out,
                int n)
{
    // per-warp staging: 16 points * 15 floats (reused feats -> dfeats)
    __shared__ __align__(16) float stage[8][16 * 15];

    int lane    = threadIdx.x & 31;
    int warp    = threadIdx.x >> 5;
    int warp_p0 = blockIdx.x * 128 + warp * 16;   // 16 points per warp
    if (warp_p0 >= n) return;
    int pl   = lane >> 1;          // point slot in warp: 0..15
    int half = lane & 1;           // cz for this lane's 4 corners
    int i = warp_p0 + pl;
    bool valid = (i < n);
    int ic = valid ? i : (n - 1);

    // Fractional evict_last: pin a stable ~half of the feat table in L2.
    uint64_t pol;
    asm volatile("createpolicy.fractional.L2::evict_last.b64 %0, 0.5;" : "=l"(pol));

    // ---- cell + frac (bit-exact: multiply by reciprocal like XLA) ----
    float ux = x[3 * ic + 0] * INV_V;
    float uy = x[3 * ic + 1] * INV_V;
    float uz = x[3 * ic + 2] * INV_V;
    float fux = floorf(ux), fuy = floorf(uy), fuz = floorf(uz);
    int xi0 = (int)fux, yi0 = (int)fuy, zi0 = (int)fuz;
    float fx = ux - fux, fy = uy - fuy, fz = uz - fuz;

    int lx0 = xi0 & 7, ly0 = yi0 & 7, lz0 = zi0 & 7;
    int bx0 = xi0 >> 3, by0 = yi0 >> 3, bz0 = zi0 >> 3;

    bool fast = (lx0 < 7) & (ly0 < 7) & (lz0 < 7) &
                ((unsigned)bx0 < GG) & ((unsigned)by0 < GG) & ((unsigned)bz0 < GG);

    // ---- this lane's 4 record element-offsets (corners (cx,cy), cz=half) ----
    int  e[4];
    bool okh;
    if (fast) {
        int b = __ldg(&btab[(bx0 * GG + by0) * GG + bz0]);
        okh = (b >= 0);
        int base = (max(b, 0) * STRIDE_ + (lx0 * RR + ly0) * RR + lz0 + half) * FF;
        e[0] = base;             // cx=0 cy=0
        e[1] = base + 8 * FF;    // cx=0 cy=1
        e[2] = base + 64 * FF;   // cx=1 cy=0
        e[3] = base + 72 * FF;   // cx=1 cy=1
    } else {
        okh = true;
#pragma unroll
        for (int c = 0; c < 4; ++c) {
            int cx = (c >> 1) & 1, cy = c & 1;
            int gx = xi0 + cx, gy = yi0 + cy, gz = zi0 + half;
            int bx = gx >> 3, by = gy >> 3, bz = gz >> 3;
            int lx = gx & 7,  ly = gy & 7,  lz = gz & 7;
            bool inb = ((unsigned)bx < GG) & ((unsigned)by < GG) & ((unsigned)bz < GG);
            int b = -1;
            if (inb) b = __ldg(&btab[(bx * GG + by) * GG + bz]);
            okh &= inb & (b >= 0);
            e[c] = (max(b, 0) * STRIDE_ + (lx * RR + ly) * RR + lz) * FF;
        }
    }
    okh &= valid;
    bool ok = okh & (bool)__shfl_xor_sync(0xFFFFFFFFu, (unsigned)okh, 1);

    // ---- gather: batch ALL 8 cache-hinted LDG.128 before consuming ----
    float acc[FF] = {0, 0, 0, 0, 0};
    float gax[FF] = {0, 0, 0, 0, 0};
    float gay[FF] = {0, 0, 0, 0, 0};
    float gaz[FF] = {0, 0, 0, 0, 0};
    if (ok) {
        float4 ra[4], rb[4];
#pragma unroll
        for (int c = 0; c < 4; ++c) {
            const char* p = (const char*)feat + (((size_t)e[c] * 4) & ~(size_t)15);
            ra[c] = ldg_el(p, pol);
            rb[c] = ldg_el(p + 16, pol);
        }
        float ox = 1.0f - fx, oy = 1.0f - fy, oz = 1.0f - fz;
        float pzw = half ? fz : oz;
        float sz  = half ? 1.0f : -1.0f;
#pragma unroll
        for (int c = 0; c < 4; ++c) {
            // extract 5 floats from the two aligned float4s
            int s = e[c] & 3;
            bool hi = (s & 2) != 0;
            float b0 = hi ? ra[c].z : ra[c].x;
            float b1 = hi ? ra[c].w : ra[c].y;
            float b2 = hi ? rb[c].x : ra[c].z;
            float b3 = hi ? rb[c].y : ra[c].w;
            float b4 = hi ? rb[c].z : rb[c].x;
            float b5 = hi ? rb[c].w : rb[c].y;
            bool od = (s & 1) != 0;
            float v0 = od ? b1 : b0;
            float v1 = od ? b2 : b1;
            float v2 = od ? b3 : b2;
            float v3 = od ? b4 : b3;
            float v4 = od ? b5 : b4;

            int cx = (c >> 1) & 1, cy = c & 1;
            float pxw = cx ? fx : ox;
            float pyw = cy ? fy : oy;
            float sx  = cx ? 1.0f : -1.0f;
            float sy  = cy ? 1.0f : -1.0f;
            float w   = pxw * pyw * pzw;
            float dwx = sx * pyw * pzw;
            float dwy = pxw * sy * pzw;
            float dwz = pxw * pyw * sz;
            acc[0] += w * v0;  acc[1] += w * v1;  acc[2] += w * v2;
            acc[3] += w * v3;  acc[4] += w * v4;
            gax[0] += dwx * v0; gax[1] += dwx * v1; gax[2] += dwx * v2;
            gax[3] += dwx * v3; gax[4] += dwx * v4;
            gay[0] += dwy * v0; gay[1] += dwy * v1; gay[2] += dwy * v2;
            gay[3] += dwy * v3; gay[4] += dwy * v4;
            gaz[0] += dwz * v0; gaz[1] += dwz * v1; gaz[2] += dwz * v2;
            gaz[3] += dwz * v3; gaz[4] += dwz * v4;
        }
    }

    // ---- pair reduce (butterfly: both lanes end with the full sums) ----
#pragma unroll
    for (int f = 0; f < FF; ++f) {
        acc[f] += __shfl_xor_sync(0xFFFFFFFFu, acc[f], 1);
        gax[f] += __shfl_xor_sync(0xFFFFFFFFu, gax[f], 1);
        gay[f] += __shfl_xor_sync(0xFFFFFFFFu, gay[f], 1);
        gaz[f] += __shfl_xor_sync(0xFFFFFFFFu, gaz[f], 1);
    }

    size_t n_sz = (size_t)n;
    // ---- mask: even lanes write 16 consecutive floats ----
    if (valid && half == 0)
        __stcs(out + n_sz * (FF + FF * 3) + i, ok ? 1.0f : 0.0f);

    float* sw = stage[warp];
    bool full_warp = (warp_p0 + 16 <= n);

    // ---- stage: even lane writes feats (5), odd lane writes dfeats (15) ----
    if (full_warp) {
        if (half == 0) {
#pragma unroll
            for (int f = 0; f < FF; ++f) sw[pl * FF + f] = acc[f];
        }
        __syncwarp();
        {   // feats: 16*5 = 80 floats = 20 float4
            const float4* src = (const float4*)sw;
            float4* dst = (float4*)(out + (size_t)warp_p0 * FF);
            if (lane < 20) __stcs(dst + lane, src[lane]);
        }
        __syncwarp();
        if (half == 1) {
#pragma unroll
            for (int f = 0; f < FF; ++f) {
                sw[pl * 15 + f * 3 + 0] = gax[f] * INV_V;
                sw[pl * 15 + f * 3 + 1] = gay[f] * INV_V;
                sw[pl * 15 + f * 3 + 2] = gaz[f] * INV_V;
            }
        }
        __syncwarp();
        {   // dfeats: 16*15 = 240 floats = 60 float4
            const float4* src = (const float4*)sw;
            float4* dst = (float4*)(out + n_sz * FF + (size_t)warp_p0 * 15);
            __stcs(dst + lane, src[lane]);
            if (lane < 28) __stcs(dst + lane + 32, src[lane + 32]);
        }
    } else if (valid && half == 0) {
        // tail fallback (unused: n % 128 == 0 for N=2M)
#pragma unroll
        for (int f = 0; f < FF; ++f) out[(size_t)i * FF + f] = acc[f];
        float* dfe = out + n_sz * FF + (size_t)i * 15;
#pragma unroll
        for (int f = 0; f < FF; ++f) {
            dfe[f * 3 + 0] = gax[f] * INV_V;
            dfe[f * 3 + 1] = gay[f] * INV_V;
            dfe[f * 3 + 2] = gaz[f] * INV_V;
        }
    }
}

extern "C" void kernel_launch(void* const* d_in, const int* in_sizes, int n_in,
                              void* d_out, int out_size)
{
    const float* x    = (const float*)d_in[0];
    const float* feat = (const float*)d_in[1];
    const int*   btab = (const int*)d_in[2];
    float*       out  = (float*)d_out;

    int n = in_sizes[0] / 3;
    int threads = 256;                       // 128 points per block
    int blocks = (n + 127) / 128;
    hashgrid_kernel<<<blocks, threads>>>(x, feat, btab, out, n);
}